// round 11
// baseline (speedup 1.0000x reference)
#include <cuda_runtime.h>

#define N_ 4
#define C_ 128
#define T_ 512
#define V_ 25
#define H_ 16
#define O_ 128
#define EPS_ 1e-5f
#define YCNT 51200.0f   // N*T*V

typedef unsigned long long ull;

// ---------------- scratch ----------------------------------------------------
__device__ float g_q[N_ * T_ * H_];          // [n][t][h]
__device__ float g_k[N_ * T_ * H_];          // [n][t][h]
__device__ float g_wvt[C_ * O_];             // [c][o]
__device__ float g_v[N_ * T_ * O_ * 32];     // [n][t][o][32] (25 data + zeros)
__device__ float g_vsum[N_ * O_ * 32];       // [n][o][32]
__device__ float g_y[(size_t)N_ * O_ * T_ * 26]; // [n][o][g][26]
__device__ float g_chsum[O_];
__device__ float g_chsq[O_];

// ---------------- helpers -----------------------------------------------------
__device__ __forceinline__ ull ffma2(ull a, ull b, ull c) {
    ull d; asm("fma.rn.f32x2 %0, %1, %2, %3;" : "=l"(d) : "l"(a), "l"(b), "l"(c)); return d;
}
__device__ __forceinline__ ull fmul2(ull a, ull b) {
    ull d; asm("mul.rn.f32x2 %0, %1, %2;" : "=l"(d) : "l"(a), "l"(b)); return d;
}
__device__ __forceinline__ ull fadd2(ull a, ull b) {
    ull d; asm("add.rn.f32x2 %0, %1, %2;" : "=l"(d) : "l"(a), "l"(b)); return d;
}
__device__ __forceinline__ ull dup2(float x) {
    ull d; asm("mov.b64 %0, {%1, %1};" : "=l"(d) : "f"(x)); return d;
}
__device__ __forceinline__ ull pack2(float x, float y) {
    ull d; asm("mov.b64 %0, {%1, %2};" : "=l"(d) : "f"(x), "f"(y)); return d;
}
__device__ __forceinline__ float2 unpack2(ull a) {
    float2 r; asm("mov.b64 {%0, %1}, %2;" : "=f"(r.x), "=f"(r.y) : "l"(a)); return r;
}
__device__ __forceinline__ float tanh_fast(float x) {
    float r; asm("tanh.approx.f32 %0, %1;" : "=f"(r) : "f"(x)); return r;
}

// ---------------- K1: q,k + housekeeping --------------------------------------
__global__ void qk_kernel(const float* __restrict__ x,
                          const float* __restrict__ Wq, const float* __restrict__ bq,
                          const float* __restrict__ Wk, const float* __restrict__ bk,
                          const float* __restrict__ Wv) {
    __shared__ float xm[C_];
    int b = blockIdx.x; int n = b >> 9; int t = b & 511;
    int tid = threadIdx.x;
    int c = tid;

    if (b < 128) {
        g_vsum[b * 128 + tid] = 0.f;
    } else if (b == 128) {
        g_chsum[tid] = 0.f; g_chsq[tid] = 0.f;
    } else if (b >= 256 && b < 384) {
        int i = (b - 256) * 128 + tid;
        int o = i >> 7, cc = i & 127;
        g_wvt[cc * O_ + o] = Wv[i];
    }

    const float* xp = x + ((n * C_ + c) * T_ + t) * V_;
    float s = 0.f;
#pragma unroll
    for (int v = 0; v < V_; v++) s += xp[v];
    xm[c] = s * (1.0f / 25.0f);
    __syncthreads();
    if (tid < 32) {
        int h = tid & 15;
        bool isQ = tid < 16;
        const float* W = isQ ? Wq : Wk;
        float acc = isQ ? bq[h] : bk[h];
#pragma unroll 8
        for (int cc = 0; cc < C_; cc++) acc += W[h * C_ + cc] * xm[cc];
        float* dst = isQ ? g_q : g_k;
        dst[(n * T_ + t) * H_ + h] = acc;
    }
}

// ---------------- K2: v projection --------------------------------------------
__global__ void v_kernel(const float* __restrict__ x, const float* __restrict__ bv) {
    __shared__ float xs[C_][28];
    int b = blockIdx.x; int n = b >> 9; int t = b & 511;
    int o = threadIdx.x;
    {
        const float* xp = x + ((n * C_ + o) * T_ + t) * V_;
#pragma unroll
        for (int v = 0; v < V_; v++) xs[o][v] = xp[v];
        xs[o][25] = 0.f; xs[o][26] = 0.f; xs[o][27] = 0.f;
    }
    __syncthreads();
    ull acc[13];
    ull binit = dup2(bv[o]);
#pragma unroll
    for (int j = 0; j < 13; j++) acc[j] = binit;
    for (int c = 0; c < C_; c++) {
        ull wd = dup2(g_wvt[c * O_ + o]);
        const ulonglong2* xr = (const ulonglong2*)xs[c];
#pragma unroll
        for (int j = 0; j < 6; j++) {
            ulonglong2 p = xr[j];
            acc[2 * j]     = ffma2(wd, p.x, acc[2 * j]);
            acc[2 * j + 1] = ffma2(wd, p.y, acc[2 * j + 1]);
        }
        acc[12] = ffma2(wd, *((const ull*)xs[c] + 12), acc[12]);
    }
    float* row = g_v + (((size_t)(n * T_ + t)) * O_ + o) * 32;
#pragma unroll
    for (int j = 0; j < 12; j++) {
        float2 u = unpack2(acc[j]);
        row[2 * j] = u.x; row[2 * j + 1] = u.y;
    }
    { float2 u = unpack2(acc[12]); row[24] = u.x; }
#pragma unroll
    for (int p = 25; p < 32; p++) row[p] = 0.f;
}

// ---------------- K3: vsum ------------------------------------------------------
__global__ void vsum_kernel() {
    __shared__ float red[8][33];
    int bx = blockIdx.x;
    int n = bx >> 8, o = (bx >> 1) & 127, half = bx & 1;
    int tid = threadIdx.x;
    int tsub = tid >> 5, comp = tid & 31;
    int t0 = half * 256 + tsub * 32;
    const float* base = g_v + (((size_t)(n * T_ + t0)) * O_ + o) * 32 + comp;
    float a0 = 0.f, a1 = 0.f, a2 = 0.f, a3 = 0.f;
#pragma unroll
    for (int u = 0; u < 32; u += 4) {
        a0 += base[(size_t)(u + 0) * O_ * 32];
        a1 += base[(size_t)(u + 1) * O_ * 32];
        a2 += base[(size_t)(u + 2) * O_ * 32];
        a3 += base[(size_t)(u + 3) * O_ * 32];
    }
    red[tsub][comp] = (a0 + a1) + (a2 + a3);
    __syncthreads();
    if (tsub == 0) {
        float s = 0.f;
#pragma unroll
        for (int r = 0; r < 8; r++) s += red[r][comp];
        atomicAdd(&g_vsum[(n * O_ + o) * 32 + comp], s);
    }
}

// ---------------- K4: fused attention — o-tile 32, g-tile 8 ---------------------
// 512 threads, tile (n, o32, g8). grid 1024 = n4 x ot4 x gt64. 2 blocks/SM.
#define TCH 8
#define NCHUNK (T_ / TCH)            // 64
#define GT 8
#define OT 32
#define SROW 132                     // 8tt*16h + 4 pad
#define AROW 68                      // 8tt*8g + 4 pad
#define SBUF (GT * SROW)             // 1056
#define ABUF (OT * AROW)             // 2176
#define SM_SS 8192
#define SM_AS (SM_SS + 2 * SBUF)     // 10304
#define SM_TOT (SM_AS + 2 * ABUF)    // 14656 floats = 58624 B

// tanh stage: thread = (g8, tt4, h16); handles tt and tt+4
__device__ __forceinline__ void a_stage(const float* __restrict__ k_s, float* __restrict__ Sb,
                                        float qv, int gA, int ttA, int hA, int cc) {
    const float* kp = k_s + cc * TCH * 16 + ttA * 16 + hA;
    float* so = Sb + gA * SROW + ttA * 16 + hA;
    so[0]  = tanh_fast(qv - kp[0]);
    so[64] = tanh_fast(qv - kp[64]);
}

// B stage: thread = (o32, tt8, gh2); computes A[o][tt][gh*4..+3]
__device__ __forceinline__ void b_stage(const float* __restrict__ Sb, float* __restrict__ Ab,
                                        const ull* __restrict__ w, int oB, int ttB, int gh) {
    float outv[4];
    const float* srow = Sb + ttB * 16;
#pragma unroll
    for (int i = 0; i < 4; i++) {
        int g = gh * 4 + i;
        const ulonglong2* sp = (const ulonglong2*)(srow + g * SROW);
        ulonglong2 s0 = sp[0], s1 = sp[1];
        ull a0 = fmul2(w[0], s0.x);  a0 = ffma2(w[1], s0.y, a0);
        a0 = ffma2(w[2], s1.x, a0);  a0 = ffma2(w[3], s1.y, a0);
        ulonglong2 s2 = sp[2], s3 = sp[3];
        ull a1 = fmul2(w[4], s2.x);  a1 = ffma2(w[5], s2.y, a1);
        a1 = ffma2(w[6], s3.x, a1);  a1 = ffma2(w[7], s3.y, a1);
        float2 u = unpack2(fadd2(a0, a1));
        outv[i] = u.x + u.y;
    }
    *(float4*)(Ab + oB * AROW + ttB * 8 + gh * 4) =
        make_float4(outv[0], outv[1], outv[2], outv[3]);
}

// C stage: thread = (o32, v-pair 13); acc0/acc1 = 4 g-pairs (8 g) for v0/v1
// two tt per iteration for MLP=4 on the A loads
__device__ __forceinline__ void c_stage(const float* __restrict__ Ab, int oC,
                                        const ull* __restrict__ vc,
                                        ull* __restrict__ acc0, ull* __restrict__ acc1) {
    const float* arow = Ab + oC * AROW;
#pragma unroll
    for (int tt = 0; tt < TCH; tt += 2) {
        const ulonglong2* ap = (const ulonglong2*)(arow + tt * 8);
        ulonglong2 p0 = ap[0], p1 = ap[1];   // tt:   g0..3, g4..7
        ulonglong2 q0 = ap[2], q1 = ap[3];   // tt+1: g0..3, g4..7
        float2 v0 = unpack2(vc[tt]);
        float2 v1 = unpack2(vc[tt + 1]);
        ull d00 = dup2(v0.x), d01 = dup2(v0.y);
        ull d10 = dup2(v1.x), d11 = dup2(v1.y);
        acc0[0] = ffma2(p0.x, d00, acc0[0]);
        acc0[1] = ffma2(p0.y, d00, acc0[1]);
        acc0[2] = ffma2(p1.x, d00, acc0[2]);
        acc0[3] = ffma2(p1.y, d00, acc0[3]);
        acc1[0] = ffma2(p0.x, d01, acc1[0]);
        acc1[1] = ffma2(p0.y, d01, acc1[1]);
        acc1[2] = ffma2(p1.x, d01, acc1[2]);
        acc1[3] = ffma2(p1.y, d01, acc1[3]);
        acc0[0] = ffma2(q0.x, d10, acc0[0]);
        acc0[1] = ffma2(q0.y, d10, acc0[1]);
        acc0[2] = ffma2(q1.x, d10, acc0[2]);
        acc0[3] = ffma2(q1.y, d10, acc0[3]);
        acc1[0] = ffma2(q0.x, d11, acc1[0]);
        acc1[1] = ffma2(q0.y, d11, acc1[1]);
        acc1[2] = ffma2(q1.x, d11, acc1[2]);
        acc1[3] = ffma2(q1.y, d11, acc1[3]);
    }
}

__global__ void __launch_bounds__(512, 2)
attn_kernel(const float* __restrict__ Wr, const float* __restrict__ br) {
    extern __shared__ float sm[];
    float* k_s = sm;
    float* S_s = sm + SM_SS;
    float* A_s = sm + SM_AS;

    int bx = blockIdx.x;
    int gt = bx & 63, ot = (bx >> 6) & 3, n = bx >> 8;
    int o_base = ot * OT, g_base = gt * GT;
    int tid = threadIdx.x;

    // roles
    int hA = tid & 15, ttA = (tid >> 4) & 3, gA = tid >> 6;   // tanh (2 tt each)
    int oB = tid & 31, ttB = (tid >> 5) & 7, gh = tid >> 8;   // B (4 g each)
    int oC = tid / 13, jC = tid - oC * 13;                    // C (tid<416)
    bool actC = tid < 416;

    // load k slice (2048 float4)
    {
        const float4* kg = (const float4*)(g_k + n * T_ * H_);
        float4* k4 = (float4*)k_s;
#pragma unroll
        for (int i = 0; i < 4; i++) k4[tid + i * 512] = kg[tid + i * 512];
    }
    float qv = g_q[(n * T_ + g_base + gA) * H_ + hA];

    ull w[8];
    {
        const ull* wp = (const ull*)(Wr + (o_base + oB) * H_);
#pragma unroll
        for (int j = 0; j < 8; j++) w[j] = wp[j];
    }

    ull acc0[4], acc1[4];
    ull vcur[8];
    const float* vbase = actC
        ? g_v + (((size_t)n * T_) * O_ + o_base + oC) * 32 + 2 * jC
        : g_v;
    if (actC) {
        float brv = br[o_base + oC];
        const float* vs = g_vsum + (n * O_ + o_base + oC) * 32 + 2 * jC;
        ull i0 = dup2(brv * vs[0]);
        ull i1 = dup2(brv * vs[1]);
#pragma unroll
        for (int p = 0; p < 4; p++) { acc0[p] = i0; acc1[p] = i1; }
#pragma unroll
        for (int tt = 0; tt < TCH; tt++)
            vcur[tt] = *(const ull*)(vbase + (size_t)tt * O_ * 32);
    }
    __syncthreads();   // k_s visible

    // prologue
    a_stage(k_s, S_s, qv, gA, ttA, hA, 0);           // S(0) -> buf0
    __syncthreads();
    a_stage(k_s, S_s + SBUF, qv, gA, ttA, hA, 1);    // S(1) -> buf1
    b_stage(S_s, A_s, w, oB, ttB, gh);               // A(0) -> buf0
    __syncthreads();

    // main loop: ONE barrier per chunk
    for (int c = 0; c < NCHUNK; c++) {
        int ab = c & 1;
        if (c < NCHUNK - 2)
            a_stage(k_s, S_s + ab * SBUF, qv, gA, ttA, hA, c + 2);
        if (c < NCHUNK - 1)
            b_stage(S_s + (ab ^ 1) * SBUF, A_s + (ab ^ 1) * ABUF, w, oB, ttB, gh);
        if (actC) {
            c_stage(A_s + ab * ABUF, oC, vcur, acc0, acc1);
            if (c < NCHUNK - 1) {
                const float* vb2 = vbase + (size_t)(c + 1) * TCH * O_ * 32;
#pragma unroll
                for (int tt = 0; tt < TCH; tt++)
                    vcur[tt] = *(const ull*)(vb2 + (size_t)tt * O_ * 32);
            }
        }
        __syncthreads();
    }

    // ---- epilogue: y writes + BN partial stats ----
    float sum = 0.f, sq = 0.f;
    if (actC) {
        int o0 = o_base + oC;
        float* ybase = g_y + (((size_t)(n * O_ + o0)) * T_ + g_base) * 26 + 2 * jC;
#pragma unroll
        for (int p = 0; p < 4; p++) {
            float2 u0 = unpack2(acc0[p]);   // (g=2p,v0),(g=2p+1,v0)
            float2 u1 = unpack2(acc1[p]);   // (g=2p,v1),(g=2p+1,v1)
            *(ull*)(ybase + (2 * p) * 26)     = pack2(u0.x, u1.x);
            *(ull*)(ybase + (2 * p + 1) * 26) = pack2(u0.y, u1.y);
            sum += u0.x + u0.y + u1.x + u1.y;
            sq  += u0.x * u0.x + u0.y * u0.y + u1.x * u1.x + u1.y * u1.y;
        }
    }
    __syncthreads();
    float* red = sm;
    if (tid < 64) red[tid] = 0.f;
    __syncthreads();
    if (actC) {
        atomicAdd(&red[oC], sum);
        atomicAdd(&red[32 + oC], sq);
    }
    __syncthreads();
    if (tid < 32)       atomicAdd(&g_chsum[o_base + tid], red[tid]);
    else if (tid < 64)  atomicAdd(&g_chsq[o_base + tid - 32], red[tid]);
}

// ---------------- K5: BN + residual + ReLU ----------------------------------------
__global__ void bn_kernel(const float* __restrict__ x,
                          const float* __restrict__ gamma, const float* __restrict__ beta,
                          float* __restrict__ out) {
    int bx = blockIdx.x;
    int n = bx >> 7, o = bx & 127;
    int tid = threadIdx.x;
    float mu  = g_chsum[o] * (1.0f / YCNT);
    float var = g_chsq[o] * (1.0f / YCNT) - mu * mu;
    float r = rsqrtf(var + EPS_);
    float gam = gamma[o] * r;
    float bet = beta[o] - mu * gam;
    const float* xb = x + (((size_t)(n * C_ + o)) * T_) * V_;
    const float* yb = g_y + ((size_t)(n * O_ + o)) * T_ * 26;
    float* ob = out + (((size_t)(n * O_ + o)) * T_) * V_;
#pragma unroll
    for (int i = 0; i < 25; i++) {
        int e = tid + i * 512;
        int t = (int)(((unsigned)e * 5243u) >> 17);
        float yv = yb[e + t];
        float val = yv * gam + bet + xb[e];
        ob[e] = fmaxf(val, 0.f);
    }
}

// ---------------- launcher ----------------------------------------------------------
extern "C" void kernel_launch(void* const* d_in, const int* in_sizes, int n_in,
                              void* d_out, int out_size) {
    const float* x     = (const float*)d_in[0];
    const float* Wq    = (const float*)d_in[1];
    const float* bq    = (const float*)d_in[2];
    const float* Wk    = (const float*)d_in[3];
    const float* bk    = (const float*)d_in[4];
    const float* Wv    = (const float*)d_in[5];
    const float* bv    = (const float*)d_in[6];
    const float* Wr    = (const float*)d_in[7];
    const float* br    = (const float*)d_in[8];
    const float* gamma = (const float*)d_in[9];
    const float* beta  = (const float*)d_in[10];
    float* out = (float*)d_out;

    const int smem_bytes = SM_TOT * 4;   // 58624
    cudaFuncSetAttribute(attn_kernel, cudaFuncAttributeMaxDynamicSharedMemorySize, smem_bytes);

    qk_kernel<<<N_ * T_, 128>>>(x, Wq, bq, Wk, bk, Wv);   // 1 (+housekeeping)
    v_kernel<<<N_ * T_, 128>>>(x, bv);                     // 2
    vsum_kernel<<<1024, 256>>>();                          // 3
    attn_kernel<<<1024, 512, smem_bytes>>>(Wr, br);        // 4  <- profiled
    bn_kernel<<<512, 512>>>(x, gamma, beta, out);          // 5
}

// round 12
// speedup vs baseline: 1.2161x; 1.2161x over previous
#include <cuda_runtime.h>

#define N_ 4
#define C_ 128
#define T_ 512
#define V_ 25
#define H_ 16
#define O_ 128
#define EPS_ 1e-5f
#define YCNT 51200.0f   // N*T*V

typedef unsigned long long ull;

// ---------------- scratch ----------------------------------------------------
__device__ float g_q[N_ * T_ * H_];          // [n][t][h]
__device__ float g_k[N_ * T_ * H_];          // [n][t][h]
__device__ float g_wvt[C_ * O_];             // [c][o]
__device__ float g_v[N_ * T_ * O_ * 32];     // [n][t][o][32] (25 data + zeros)
__device__ float g_vsum[N_ * O_ * 32];       // [n][o][32]
__device__ float g_y[(size_t)N_ * O_ * T_ * 26]; // [n][o][g][26]
__device__ float g_chsum[O_];
__device__ float g_chsq[O_];

// ---------------- helpers -----------------------------------------------------
__device__ __forceinline__ ull ffma2(ull a, ull b, ull c) {
    ull d; asm("fma.rn.f32x2 %0, %1, %2, %3;" : "=l"(d) : "l"(a), "l"(b), "l"(c)); return d;
}
__device__ __forceinline__ ull fmul2(ull a, ull b) {
    ull d; asm("mul.rn.f32x2 %0, %1, %2;" : "=l"(d) : "l"(a), "l"(b)); return d;
}
__device__ __forceinline__ ull fadd2(ull a, ull b) {
    ull d; asm("add.rn.f32x2 %0, %1, %2;" : "=l"(d) : "l"(a), "l"(b)); return d;
}
__device__ __forceinline__ ull dup2(float x) {
    ull d; asm("mov.b64 %0, {%1, %1};" : "=l"(d) : "f"(x)); return d;
}
__device__ __forceinline__ float2 unpack2(ull a) {
    float2 r; asm("mov.b64 {%0, %1}, %2;" : "=f"(r.x), "=f"(r.y) : "l"(a)); return r;
}
__device__ __forceinline__ float tanh_fast(float x) {
    float r; asm("tanh.approx.f32 %0, %1;" : "=f"(r) : "f"(x)); return r;
}

// ---------------- K0: prep (zero accumulators, transpose Wv) -------------------
// 128 blocks x 128 threads
__global__ void prep_kernel(const float* __restrict__ Wv) {
    int b = blockIdx.x, tid = threadIdx.x;
    int i = b * 128 + tid;          // 0..16383
    g_vsum[i & (N_ * O_ * 32 - 1)] = 0.f;
    int o = i >> 7, c = i & 127;
    g_wvt[c * O_ + o] = Wv[i];
    if (b == 0) { g_chsum[tid] = 0.f; g_chsq[tid] = 0.f; }
}

// ---------------- K1: fused x-load -> xm -> q,k -> v ---------------------------
// 2048 blocks = (n,t), 128 threads
__global__ void qkv_kernel(const float* __restrict__ x,
                           const float* __restrict__ Wq, const float* __restrict__ bq,
                           const float* __restrict__ Wk, const float* __restrict__ bk,
                           const float* __restrict__ bv) {
    __shared__ float xs[C_][28];
    __shared__ float xm[C_];
    int b = blockIdx.x; int n = b >> 9; int t = b & 511;
    int o = threadIdx.x;            // doubles as channel index c for loading
    {
        const float* xp = x + ((n * C_ + o) * T_ + t) * V_;
        float s = 0.f;
#pragma unroll
        for (int v = 0; v < V_; v++) { float xv = xp[v]; xs[o][v] = xv; s += xv; }
        xs[o][25] = 0.f; xs[o][26] = 0.f; xs[o][27] = 0.f;
        xm[o] = s * (1.0f / 25.0f);
    }
    __syncthreads();

    // q,k (threads 0..31)
    if (o < 32) {
        int h = o & 15;
        bool isQ = o < 16;
        const float* W = isQ ? Wq : Wk;
        float acc = isQ ? bq[h] : bk[h];
#pragma unroll 8
        for (int cc = 0; cc < C_; cc++) acc += W[h * C_ + cc] * xm[cc];
        float* dst = isQ ? g_q : g_k;
        dst[(n * T_ + t) * H_ + h] = acc;
    }

    // v projection (all 128 threads, thread = o)
    ull acc[13];
    ull binit = dup2(bv[o]);
#pragma unroll
    for (int j = 0; j < 13; j++) acc[j] = binit;
    for (int c = 0; c < C_; c++) {
        ull wd = dup2(g_wvt[c * O_ + o]);
        const ulonglong2* xr = (const ulonglong2*)xs[c];
#pragma unroll
        for (int j = 0; j < 6; j++) {
            ulonglong2 p = xr[j];
            acc[2 * j]     = ffma2(wd, p.x, acc[2 * j]);
            acc[2 * j + 1] = ffma2(wd, p.y, acc[2 * j + 1]);
        }
        acc[12] = ffma2(wd, *((const ull*)xs[c] + 12), acc[12]);
    }
    float* row = g_v + (((size_t)(n * T_ + t)) * O_ + o) * 32;
#pragma unroll
    for (int j = 0; j < 12; j++) {
        float2 u = unpack2(acc[j]);
        row[2 * j] = u.x; row[2 * j + 1] = u.y;
    }
    { float2 u = unpack2(acc[12]); row[24] = u.x; }
#pragma unroll
    for (int p = 25; p < 32; p++) row[p] = 0.f;
}

// ---------------- K2: vsum ------------------------------------------------------
__global__ void vsum_kernel() {
    __shared__ float red[8][33];
    int bx = blockIdx.x;
    int n = bx >> 8, o = (bx >> 1) & 127, half = bx & 1;
    int tid = threadIdx.x;
    int tsub = tid >> 5, comp = tid & 31;
    int t0 = half * 256 + tsub * 32;
    const float* base = g_v + (((size_t)(n * T_ + t0)) * O_ + o) * 32 + comp;
    float a0 = 0.f, a1 = 0.f, a2 = 0.f, a3 = 0.f;
#pragma unroll
    for (int u = 0; u < 32; u += 4) {
        a0 += base[(size_t)(u + 0) * O_ * 32];
        a1 += base[(size_t)(u + 1) * O_ * 32];
        a2 += base[(size_t)(u + 2) * O_ * 32];
        a3 += base[(size_t)(u + 3) * O_ * 32];
    }
    red[tsub][comp] = (a0 + a1) + (a2 + a3);
    __syncthreads();
    if (tsub == 0) {
        float s = 0.f;
#pragma unroll
        for (int r = 0; r < 8; r++) s += red[r][comp];
        atomicAdd(&g_vsum[(n * O_ + o) * 32 + comp], s);
    }
}

// ---------------- K3: fused attention — R9 configuration (proven 499us) ---------
#define TCH 8
#define NCHUNK (T_ / TCH)            // 64
#define ROWP 132
#define SM_SS 8192
#define SM_AS (SM_SS + 2 * 16 * ROWP)   // 12416
#define SM_TOT (SM_AS + 2 * 16 * ROWP)  // 16640 floats = 66560 B
#define SBUF (16 * ROWP)
#define ABUF (16 * ROWP)

// tanh stage: 4 tt per thread
__device__ __forceinline__ void a_stage4(const float* __restrict__ k_s, float* __restrict__ Sb,
                                         float qv, int gA, int hA, int tth, int cc) {
    const float* kp = k_s + cc * TCH * 16 + tth * 64 + hA;
    float* so = Sb + gA * ROWP + tth * 64 + hA;
#pragma unroll
    for (int tt = 0; tt < 4; tt++) so[tt * 16] = tanh_fast(qv - kp[tt * 16]);
}

// B stage: 4 g per thread
__device__ __forceinline__ void b_stage4(const float* __restrict__ Sb, float* __restrict__ Ab,
                                         const ull* __restrict__ w, int oB, int ttB, int gq) {
    float outv[4];
    const float* srow = Sb + ttB * 16;
#pragma unroll
    for (int i = 0; i < 4; i++) {
        int g = gq * 4 + i;
        const ulonglong2* sp = (const ulonglong2*)(srow + g * ROWP);
        ulonglong2 s0 = sp[0], s1 = sp[1];
        ull a0 = fmul2(w[0], s0.x);  a0 = ffma2(w[1], s0.y, a0);
        a0 = ffma2(w[2], s1.x, a0);  a0 = ffma2(w[3], s1.y, a0);
        ulonglong2 s2 = sp[2], s3 = sp[3];
        ull a1 = fmul2(w[4], s2.x);  a1 = ffma2(w[5], s2.y, a1);
        a1 = ffma2(w[6], s3.x, a1);  a1 = ffma2(w[7], s3.y, a1);
        float2 u = unpack2(fadd2(a0, a1));
        outv[i] = u.x + u.y;
    }
    *(float4*)(Ab + oB * ROWP + ttB * 16 + gq * 4) =
        make_float4(outv[0], outv[1], outv[2], outv[3]);
}

// C stage: scalar v, acc = 8 f32x2 pairs over g
__device__ __forceinline__ void c_scalar(const float* __restrict__ Ab, int oC,
                                         const float* __restrict__ vc, ull* __restrict__ acc) {
    const float* arow = Ab + oC * ROWP;
#pragma unroll
    for (int tt = 0; tt < TCH; tt++) {
        const ulonglong2* ap = (const ulonglong2*)(arow + tt * 16);
        ull d = dup2(vc[tt]);
        ulonglong2 p0 = ap[0], p1 = ap[1];
        acc[0] = ffma2(p0.x, d, acc[0]);
        acc[1] = ffma2(p0.y, d, acc[1]);
        acc[2] = ffma2(p1.x, d, acc[2]);
        acc[3] = ffma2(p1.y, d, acc[3]);
        ulonglong2 p2 = ap[2], p3 = ap[3];
        acc[4] = ffma2(p2.x, d, acc[4]);
        acc[5] = ffma2(p2.y, d, acc[5]);
        acc[6] = ffma2(p3.x, d, acc[6]);
        acc[7] = ffma2(p3.y, d, acc[7]);
    }
}

__global__ void __launch_bounds__(512, 2)
attn_kernel(const float* __restrict__ Wr, const float* __restrict__ br) {
    extern __shared__ float sm[];
    float* k_s = sm;
    float* S_s = sm + SM_SS;
    float* A_s = sm + SM_AS;

    int bx = blockIdx.x;
    int gt = bx & 31, ot = (bx >> 5) & 7, n = bx >> 8;
    int o_base = ot * 16, g_base = gt * 16;
    int tid = threadIdx.x;

    // roles
    int hA = tid & 15, gA = (tid >> 4) & 15, tth = tid >> 8;   // tanh: 4 tt each
    int oB = tid & 15, ttB = (tid >> 4) & 7, gq = tid >> 7;    // B: 4 g each
    int oC = tid / 26, vC = tid - oC * 26;                     // C: scalar v (tid<416)
    bool actC = tid < 416;

    // load k slice (2048 float4)
    {
        const float4* kg = (const float4*)(g_k + n * T_ * H_);
        float4* k4 = (float4*)k_s;
#pragma unroll
        for (int i = 0; i < 4; i++) k4[tid + i * 512] = kg[tid + i * 512];
    }
    float qv = g_q[(n * T_ + g_base + gA) * H_ + hA];

    ull w[8];
    {
        const ull* wp = (const ull*)(Wr + (o_base + oB) * H_);
#pragma unroll
        for (int j = 0; j < 8; j++) w[j] = wp[j];
    }

    ull acc[8];
    float vcur[8];
    const float* vbase = actC
        ? g_v + (((size_t)n * T_) * O_ + o_base + oC) * 32 + vC
        : g_v;
    if (actC) {
        float brv = br[o_base + oC];
        float vs = g_vsum[(n * O_ + o_base + oC) * 32 + vC];
        ull i0 = dup2(brv * vs);
#pragma unroll
        for (int p = 0; p < 8; p++) acc[p] = i0;
#pragma unroll
        for (int tt = 0; tt < TCH; tt++)
            vcur[tt] = vbase[(size_t)tt * O_ * 32];
    }
    __syncthreads();   // k_s visible

    // prologue
    a_stage4(k_s, S_s, qv, gA, hA, tth, 0);           // S(0) -> buf0
    __syncthreads();
    a_stage4(k_s, S_s + SBUF, qv, gA, hA, tth, 1);    // S(1) -> buf1
    b_stage4(S_s, A_s, w, oB, ttB, gq);               // A(0) -> buf0
    __syncthreads();

    // main loop: ONE barrier per chunk
    for (int c = 0; c < NCHUNK; c++) {
        int ab = c & 1;
        if (c < NCHUNK - 2)
            a_stage4(k_s, S_s + ab * SBUF, qv, gA, hA, tth, c + 2);
        if (c < NCHUNK - 1)
            b_stage4(S_s + (ab ^ 1) * SBUF, A_s + (ab ^ 1) * ABUF, w, oB, ttB, gq);
        if (actC) {
            c_scalar(A_s + ab * ABUF, oC, vcur, acc);
            if (c < NCHUNK - 1) {
                const float* vb2 = vbase + (size_t)(c + 1) * TCH * O_ * 32;
#pragma unroll
                for (int tt = 0; tt < TCH; tt++)
                    vcur[tt] = vb2[(size_t)tt * O_ * 32];
            }
        }
        __syncthreads();
    }

    // ---- epilogue: y writes + BN partial stats ----
    float sum = 0.f, sq = 0.f;
    if (actC) {
        int o0 = o_base + oC;
        float* ybase = g_y + (((size_t)(n * O_ + o0)) * T_ + g_base) * 26 + vC;
#pragma unroll
        for (int p = 0; p < 8; p++) {
            float2 u = unpack2(acc[p]);
            ybase[(2 * p) * 26]     = u.x;
            ybase[(2 * p + 1) * 26] = u.y;
            sum += u.x + u.y;
            sq  += u.x * u.x + u.y * u.y;
        }
    }
    __syncthreads();
    float* red = sm;
    if (tid < 32) red[tid] = 0.f;
    __syncthreads();
    if (actC) {
        atomicAdd(&red[oC], sum);
        atomicAdd(&red[16 + oC], sq);
    }
    __syncthreads();
    if (tid < 16)       atomicAdd(&g_chsum[o_base + tid], red[tid]);
    else if (tid < 32)  atomicAdd(&g_chsq[o_base + tid - 16], red[tid]);
}

// ---------------- K4: BN + residual + ReLU ----------------------------------------
__global__ void bn_kernel(const float* __restrict__ x,
                          const float* __restrict__ gamma, const float* __restrict__ beta,
                          float* __restrict__ out) {
    int bx = blockIdx.x;
    int n = bx >> 7, o = bx & 127;
    int tid = threadIdx.x;
    float mu  = g_chsum[o] * (1.0f / YCNT);
    float var = g_chsq[o] * (1.0f / YCNT) - mu * mu;
    float r = rsqrtf(var + EPS_);
    float gam = gamma[o] * r;
    float bet = beta[o] - mu * gam;
    const float* xb = x + (((size_t)(n * C_ + o)) * T_) * V_;
    const float* yb = g_y + ((size_t)(n * O_ + o)) * T_ * 26;
    float* ob = out + (((size_t)(n * O_ + o)) * T_) * V_;
#pragma unroll
    for (int i = 0; i < 25; i++) {
        int e = tid + i * 512;
        int t = (int)(((unsigned)e * 5243u) >> 17);
        float yv = yb[e + t];
        float val = yv * gam + bet + xb[e];
        ob[e] = fmaxf(val, 0.f);
    }
}

// ---------------- launcher ----------------------------------------------------------
extern "C" void kernel_launch(void* const* d_in, const int* in_sizes, int n_in,
                              void* d_out, int out_size) {
    const float* x     = (const float*)d_in[0];
    const float* Wq    = (const float*)d_in[1];
    const float* bq    = (const float*)d_in[2];
    const float* Wk    = (const float*)d_in[3];
    const float* bk    = (const float*)d_in[4];
    const float* Wv    = (const float*)d_in[5];
    const float* bv    = (const float*)d_in[6];
    const float* Wr    = (const float*)d_in[7];
    const float* br    = (const float*)d_in[8];
    const float* gamma = (const float*)d_in[9];
    const float* beta  = (const float*)d_in[10];
    float* out = (float*)d_out;

    const int smem_bytes = SM_TOT * 4;   // 66560
    cudaFuncSetAttribute(attn_kernel, cudaFuncAttributeMaxDynamicSharedMemorySize, smem_bytes);

    prep_kernel<<<128, 128>>>(Wv);                              // 1
    qkv_kernel<<<N_ * T_, 128>>>(x, Wq, bq, Wk, bk, bv);        // 2 (fused qk+v)
    vsum_kernel<<<1024, 256>>>();                               // 3
    attn_kernel<<<1024, 512, smem_bytes>>>(Wr, br);             // 4  <- profiled
    bn_kernel<<<512, 512>>>(x, gamma, beta, out);               // 5
}